// round 1
// baseline (speedup 1.0000x reference)
#include <cuda_runtime.h>
#include <math.h>

#define BB 2
#define SS 2048
#define DM 768
#define NH 12
#define DH 64
#define MROWS (BB*SS)   // 4096

// ---- scratch (device globals; no allocation allowed) ----
__device__ float g_qh[(size_t)BB*NH*SS*DH];   // [B,H,S,Dh], pre-scaled by 1/8
__device__ float g_kh[(size_t)BB*NH*SS*DH];
__device__ float g_vh[(size_t)BB*NH*SS*DH];
__device__ float g_ao[(size_t)MROWS*DM];      // attention out, [B,S,H*Dh]
__device__ float g_sc[(size_t)BB*NH*SS*SS];   // scores/attn, 402 MB

// ============================================================
// Projection GEMM: C[i,j] = (sum_k X[i,k]*W[j,k] + bias[j]) * scale
// X: [4096,768] row-major, W: [768,768] row-major (torch Linear weight)
// HEAD_LAYOUT: write to [B,H,S,Dh]; else plain [4096,768].
// ============================================================
template<bool HEAD_LAYOUT>
__global__ __launch_bounds__(256)
void proj_kernel(const float* __restrict__ X, const float* __restrict__ W,
                 const float* __restrict__ bias, float* __restrict__ out,
                 float scale) {
    __shared__ float As[16][68];
    __shared__ float Bs[16][68];
    const int tx = threadIdx.x & 15, ty = threadIdx.x >> 4;
    const int row0 = blockIdx.y * 64, col0 = blockIdx.x * 64;
    float acc[4][4] = {};
    const int t = threadIdx.x;
    const int lr = t >> 2;           // 0..63
    const int lk = (t & 3) * 4;      // 0,4,8,12

    for (int k0 = 0; k0 < DM; k0 += 16) {
        float4 a = *(const float4*)&X[(size_t)(row0 + lr) * DM + k0 + lk];
        float4 b = *(const float4*)&W[(size_t)(col0 + lr) * DM + k0 + lk];
        As[lk+0][lr] = a.x; As[lk+1][lr] = a.y; As[lk+2][lr] = a.z; As[lk+3][lr] = a.w;
        Bs[lk+0][lr] = b.x; Bs[lk+1][lr] = b.y; Bs[lk+2][lr] = b.z; Bs[lk+3][lr] = b.w;
        __syncthreads();
        #pragma unroll
        for (int kk = 0; kk < 16; kk++) {
            float4 ra = *(const float4*)&As[kk][ty*4];
            float4 rb = *(const float4*)&Bs[kk][tx*4];
            float pa[4] = {ra.x, ra.y, ra.z, ra.w};
            float pb[4] = {rb.x, rb.y, rb.z, rb.w};
            #pragma unroll
            for (int i = 0; i < 4; i++)
                #pragma unroll
                for (int j = 0; j < 4; j++)
                    acc[i][j] += pa[i] * pb[j];
        }
        __syncthreads();
    }
    #pragma unroll
    for (int i = 0; i < 4; i++) {
        const int r = row0 + ty*4 + i;
        #pragma unroll
        for (int j = 0; j < 4; j++) {
            const int c = col0 + tx*4 + j;
            float v = (acc[i][j] + bias[c]) * scale;
            if (HEAD_LAYOUT) {
                const int b_ = r / SS, s_ = r % SS;
                const int h_ = c / DH, d_ = c % DH;
                out[((size_t)(b_*NH + h_)*SS + s_)*DH + d_] = v;
            } else {
                out[(size_t)r*DM + c] = v;
            }
        }
    }
}

// ============================================================
// Scores: per (b,h): SC[s,t] = sum_d Q[s,d]*K[t,d] (Q pre-scaled),
// then mask quirk: mask==0 -> 1e-12
// ============================================================
__global__ __launch_bounds__(256)
void scores_kernel(const int* __restrict__ masks) {
    const int bh = blockIdx.z;
    const int b_ = bh / NH;
    const float* Q = g_qh + (size_t)bh * SS * DH;
    const float* K = g_kh + (size_t)bh * SS * DH;
    float* SC = g_sc + (size_t)bh * SS * SS;

    __shared__ float As[16][68];
    __shared__ float Bs[16][68];
    const int tx = threadIdx.x & 15, ty = threadIdx.x >> 4;
    const int row0 = blockIdx.y * 64, col0 = blockIdx.x * 64;
    float acc[4][4] = {};
    const int t = threadIdx.x;
    const int lr = t >> 2;
    const int lk = (t & 3) * 4;

    for (int k0 = 0; k0 < DH; k0 += 16) {
        float4 a = *(const float4*)&Q[(size_t)(row0 + lr) * DH + k0 + lk];
        float4 b = *(const float4*)&K[(size_t)(col0 + lr) * DH + k0 + lk];
        As[lk+0][lr] = a.x; As[lk+1][lr] = a.y; As[lk+2][lr] = a.z; As[lk+3][lr] = a.w;
        Bs[lk+0][lr] = b.x; Bs[lk+1][lr] = b.y; Bs[lk+2][lr] = b.z; Bs[lk+3][lr] = b.w;
        __syncthreads();
        #pragma unroll
        for (int kk = 0; kk < 16; kk++) {
            float4 ra = *(const float4*)&As[kk][ty*4];
            float4 rb = *(const float4*)&Bs[kk][tx*4];
            float pa[4] = {ra.x, ra.y, ra.z, ra.w};
            float pb[4] = {rb.x, rb.y, rb.z, rb.w};
            #pragma unroll
            for (int i = 0; i < 4; i++)
                #pragma unroll
                for (int j = 0; j < 4; j++)
                    acc[i][j] += pa[i] * pb[j];
        }
        __syncthreads();
    }
    const int* M = masks + (size_t)b_ * SS * SS;
    #pragma unroll
    for (int i = 0; i < 4; i++) {
        const int r = row0 + ty*4 + i;
        #pragma unroll
        for (int j = 0; j < 4; j++) {
            const int c = col0 + tx*4 + j;
            const int m = M[(size_t)r*SS + c];
            SC[(size_t)r*SS + c] = (m == 0) ? 1e-12f : acc[i][j];
        }
    }
}

// ============================================================
// Row softmax over g_sc, in place. One block per row.
// ============================================================
__global__ __launch_bounds__(256)
void softmax_kernel() {
    float* p = g_sc + (size_t)blockIdx.x * SS;
    const int t = threadIdx.x;
    __shared__ float red[256];

    float v[8];
    float lm = -INFINITY;
    #pragma unroll
    for (int i = 0; i < 8; i++) { v[i] = p[t + i*256]; lm = fmaxf(lm, v[i]); }
    red[t] = lm; __syncthreads();
    for (int s = 128; s > 0; s >>= 1) { if (t < s) red[t] = fmaxf(red[t], red[t+s]); __syncthreads(); }
    const float m = red[0]; __syncthreads();

    float ls = 0.f;
    #pragma unroll
    for (int i = 0; i < 8; i++) { v[i] = __expf(v[i] - m); ls += v[i]; }
    red[t] = ls; __syncthreads();
    for (int s = 128; s > 0; s >>= 1) { if (t < s) red[t] += red[t+s]; __syncthreads(); }
    const float inv = 1.0f / red[0];
    #pragma unroll
    for (int i = 0; i < 8; i++) p[t + i*256] = v[i] * inv;
}

// ============================================================
// attn @ V: per (b,h): out[s,d] = sum_t P[s,t]*V[t,d]
// writes g_ao in [B,S,H*Dh] layout
// ============================================================
__global__ __launch_bounds__(256)
void attnv_kernel() {
    const int bh = blockIdx.z;
    const int b_ = bh / NH, h_ = bh % NH;
    const float* P = g_sc + (size_t)bh * SS * SS;
    const float* V = g_vh + (size_t)bh * SS * DH;

    __shared__ float As[16][68];
    __shared__ float Bs[16][68];
    const int tx = threadIdx.x & 15, ty = threadIdx.x >> 4;
    const int row0 = blockIdx.y * 64;   // query rows; col tile is the whole Dh=64
    float acc[4][4] = {};
    const int t = threadIdx.x;
    const int lr = t >> 2;          // 0..63 (A rows)
    const int lk = (t & 3) * 4;     // A k offset
    const int kr = t >> 4;          // 0..15 (B k rows)
    const int dc = (t & 15) * 4;    // B col offset

    for (int k0 = 0; k0 < SS; k0 += 16) {
        float4 a = *(const float4*)&P[(size_t)(row0 + lr) * SS + k0 + lk];
        float4 b = *(const float4*)&V[(size_t)(k0 + kr) * DH + dc];
        As[lk+0][lr] = a.x; As[lk+1][lr] = a.y; As[lk+2][lr] = a.z; As[lk+3][lr] = a.w;
        Bs[kr][dc+0] = b.x; Bs[kr][dc+1] = b.y; Bs[kr][dc+2] = b.z; Bs[kr][dc+3] = b.w;
        __syncthreads();
        #pragma unroll
        for (int kk = 0; kk < 16; kk++) {
            float4 ra = *(const float4*)&As[kk][ty*4];
            float4 rb = *(const float4*)&Bs[kk][tx*4];
            float pa[4] = {ra.x, ra.y, ra.z, ra.w};
            float pb[4] = {rb.x, rb.y, rb.z, rb.w};
            #pragma unroll
            for (int i = 0; i < 4; i++)
                #pragma unroll
                for (int j = 0; j < 4; j++)
                    acc[i][j] += pa[i] * pb[j];
        }
        __syncthreads();
    }
    #pragma unroll
    for (int i = 0; i < 4; i++) {
        const int s_ = row0 + ty*4 + i;
        #pragma unroll
        for (int j = 0; j < 4; j++) {
            const int d_ = tx*4 + j;
            g_ao[((size_t)(b_*SS + s_))*DM + h_*DH + d_] = acc[i][j];
        }
    }
}

// ============================================================
extern "C" void kernel_launch(void* const* d_in, const int* in_sizes, int n_in,
                              void* d_out, int out_size) {
    const float* q    = (const float*)d_in[0];
    const float* k    = (const float*)d_in[1];
    const float* v    = (const float*)d_in[2];
    const int*   msk  = (const int*)  d_in[3];
    const float* WQ_w = (const float*)d_in[4];
    const float* WQ_b = (const float*)d_in[5];
    const float* WK_w = (const float*)d_in[6];
    const float* WK_b = (const float*)d_in[7];
    const float* WV_w = (const float*)d_in[8];
    const float* WV_b = (const float*)d_in[9];
    const float* WO_w = (const float*)d_in[10];
    const float* WO_b = (const float*)d_in[11];
    float* out = (float*)d_out;

    float *qh, *kh, *vh, *ao;
    cudaGetSymbolAddress((void**)&qh, g_qh);
    cudaGetSymbolAddress((void**)&kh, g_kh);
    cudaGetSymbolAddress((void**)&vh, g_vh);
    cudaGetSymbolAddress((void**)&ao, g_ao);

    const float qscale = 1.0f / 8.0f;  // 1/sqrt(64)

    dim3 pg(DM/64, MROWS/64);          // (12, 64)
    proj_kernel<true><<<pg, 256>>>(q, WQ_w, WQ_b, qh, qscale);
    proj_kernel<true><<<pg, 256>>>(k, WK_w, WK_b, kh, 1.0f);
    proj_kernel<true><<<pg, 256>>>(v, WV_w, WV_b, vh, 1.0f);

    dim3 sg(SS/64, SS/64, BB*NH);      // (32, 32, 24)
    scores_kernel<<<sg, 256>>>(msk);

    softmax_kernel<<<BB*NH*SS, 256>>>();

    dim3 ag(1, SS/64, BB*NH);          // (1, 32, 24)
    attnv_kernel<<<ag, 256>>>();

    proj_kernel<false><<<pg, 256>>>(ao, WO_w, WO_b, out, 1.0f);
}

// round 3
// speedup vs baseline: 1.0131x; 1.0131x over previous
#include <cuda_runtime.h>
#include <cuda_bf16.h>
#include <cstdint>
#include <math.h>

#define BB 2
#define SS 2048
#define DM 768
#define NH 12
#define DH 64
#define MROWS (BB*SS)   // 4096

#define BLK 64          // block tile M and N
#define BK  32          // block tile K
#define SA  40          // smem row stride in bf16 elems (conflict-free for frag loads)

// ---- scratch (device globals; no allocation allowed) ----
__device__ float g_qh[(size_t)BB*NH*SS*DH];   // [B,H,S,Dh], Q pre-scaled by 1/8
__device__ float g_kh[(size_t)BB*NH*SS*DH];
__device__ float g_vh[(size_t)BB*NH*SS*DH];
__device__ float g_ao[(size_t)MROWS*DM];      // attention out, [B,S,H*Dh]
__device__ float g_sc[(size_t)BB*NH*SS*SS];   // scores/attn probs

// ------------------------------------------------------------
// bf16 split helpers
// ------------------------------------------------------------
__device__ __forceinline__ void split_store(__nv_bfloat16* H, __nv_bfloat16* L,
                                            int idx, float x) {
    __nv_bfloat16 h = __float2bfloat16(x);
    float r = x - __bfloat162float(h);
    H[idx] = h;
    L[idx] = __float2bfloat16(r);
}

__device__ __forceinline__ void mma_bf16(float c[4],
                                         uint32_t a0, uint32_t a1, uint32_t a2, uint32_t a3,
                                         uint32_t b0, uint32_t b1) {
    asm volatile(
        "mma.sync.aligned.m16n8k16.row.col.f32.bf16.bf16.f32 "
        "{%0,%1,%2,%3},{%4,%5,%6,%7},{%8,%9},{%0,%1,%2,%3};"
        : "+f"(c[0]), "+f"(c[1]), "+f"(c[2]), "+f"(c[3])
        : "r"(a0), "r"(a1), "r"(a2), "r"(a3), "r"(b0), "r"(b1));
}

// ------------------------------------------------------------
// 64x64 block GEMM mainloop, bf16x3 compensated, fp32 accum.
// A: row-major [64 rows from ptr, lda], k contiguous.
// B (TRANSB=false): row-major [n][k] (i.e. computing A @ B^T), ldb = k-stride.
// B (TRANSB=true):  row-major [k][n] (computing A @ B), ldb = n-stride.
// 128 threads = 4 warps (2x2), warp tile 32x32 = 2 m-tiles x 4 n-tiles.
// ------------------------------------------------------------
template<bool TRANSB>
__device__ __forceinline__ void gemm64(const float* __restrict__ A, int lda,
                                       const float* __restrict__ B, int ldb,
                                       int K, float acc[2][4][4]) {
    __shared__ __nv_bfloat16 Ah[BLK*SA], Al[BLK*SA];
    __shared__ __nv_bfloat16 Bh[BLK*SA], Bl[BLK*SA];

    const int tid  = threadIdx.x;
    const int lane = tid & 31, warp = tid >> 5;
    const int g = lane >> 2, t = lane & 3;
    const int wm = warp >> 1, wn = warp & 1;

    const int arow = tid >> 1;          // 0..63
    const int acb  = (tid & 1) * 16;    // 0 or 16
    const int vk   = tid >> 2;          // 0..31 (trans loader)
    const int vnb  = (tid & 3) * 16;    // 0,16,32,48

    for (int k0 = 0; k0 < K; k0 += BK) {
        // ---- stage A tile (64 x 32) ----
        #pragma unroll
        for (int j = 0; j < 4; j++) {
            float4 v = *(const float4*)&A[(size_t)arow * lda + k0 + acb + 4*j];
            int c = arow * SA + acb + 4*j;
            split_store(Ah, Al, c+0, v.x);
            split_store(Ah, Al, c+1, v.y);
            split_store(Ah, Al, c+2, v.z);
            split_store(Ah, Al, c+3, v.w);
        }
        // ---- stage B tile ----
        if (!TRANSB) {
            #pragma unroll
            for (int j = 0; j < 4; j++) {
                float4 v = *(const float4*)&B[(size_t)arow * ldb + k0 + acb + 4*j];
                int c = arow * SA + acb + 4*j;
                split_store(Bh, Bl, c+0, v.x);
                split_store(Bh, Bl, c+1, v.y);
                split_store(Bh, Bl, c+2, v.z);
                split_store(Bh, Bl, c+3, v.w);
            }
        } else {
            // B global is [k][n]; store transposed Bs[n][k]
            #pragma unroll
            for (int j = 0; j < 4; j++) {
                float4 v = *(const float4*)&B[(size_t)(k0 + vk) * ldb + vnb + 4*j];
                int n = vnb + 4*j;
                split_store(Bh, Bl, (n+0)*SA + vk, v.x);
                split_store(Bh, Bl, (n+1)*SA + vk, v.y);
                split_store(Bh, Bl, (n+2)*SA + vk, v.z);
                split_store(Bh, Bl, (n+3)*SA + vk, v.w);
            }
        }
        __syncthreads();

        // ---- compute: 2 k-chunks of 16 ----
        #pragma unroll
        for (int kc = 0; kc < BK; kc += 16) {
            uint32_t ah[2][4], al[2][4];
            #pragma unroll
            for (int i = 0; i < 2; i++) {
                int r0 = wm*32 + i*16 + g;
                ah[i][0] = *(const uint32_t*)&Ah[ r0   *SA + kc + 2*t    ];
                ah[i][1] = *(const uint32_t*)&Ah[(r0+8)*SA + kc + 2*t    ];
                ah[i][2] = *(const uint32_t*)&Ah[ r0   *SA + kc + 2*t + 8];
                ah[i][3] = *(const uint32_t*)&Ah[(r0+8)*SA + kc + 2*t + 8];
                al[i][0] = *(const uint32_t*)&Al[ r0   *SA + kc + 2*t    ];
                al[i][1] = *(const uint32_t*)&Al[(r0+8)*SA + kc + 2*t    ];
                al[i][2] = *(const uint32_t*)&Al[ r0   *SA + kc + 2*t + 8];
                al[i][3] = *(const uint32_t*)&Al[(r0+8)*SA + kc + 2*t + 8];
            }
            #pragma unroll
            for (int j = 0; j < 4; j++) {
                int n0 = wn*32 + j*8 + g;
                uint32_t bh0 = *(const uint32_t*)&Bh[n0*SA + kc + 2*t    ];
                uint32_t bh1 = *(const uint32_t*)&Bh[n0*SA + kc + 2*t + 8];
                uint32_t bl0 = *(const uint32_t*)&Bl[n0*SA + kc + 2*t    ];
                uint32_t bl1 = *(const uint32_t*)&Bl[n0*SA + kc + 2*t + 8];
                #pragma unroll
                for (int i = 0; i < 2; i++) {
                    mma_bf16(acc[i][j], ah[i][0],ah[i][1],ah[i][2],ah[i][3], bh0, bh1);
                    mma_bf16(acc[i][j], ah[i][0],ah[i][1],ah[i][2],ah[i][3], bl0, bl1);
                    mma_bf16(acc[i][j], al[i][0],al[i][1],al[i][2],al[i][3], bh0, bh1);
                }
            }
        }
        __syncthreads();
    }
}

// ------------------------------------------------------------
// Projection: out = (X @ W^T + bias) * scale; X [4096,768], W [768,768]
// ------------------------------------------------------------
template<bool HEAD_LAYOUT>
__global__ __launch_bounds__(128)
void proj_mma(const float* __restrict__ X, const float* __restrict__ W,
              const float* __restrict__ bias, float* __restrict__ out, float scale) {
    float acc[2][4][4] = {};
    const float* Ap = X + (size_t)blockIdx.y * BLK * DM;
    const float* Bp = W + (size_t)blockIdx.x * BLK * DM;
    gemm64<false>(Ap, DM, Bp, DM, DM, acc);

    const int lane = threadIdx.x & 31, warp = threadIdx.x >> 5;
    const int g = lane >> 2, t = lane & 3;
    const int wm = warp >> 1, wn = warp & 1;
    #pragma unroll
    for (int i = 0; i < 2; i++) {
        #pragma unroll
        for (int j = 0; j < 4; j++) {
            #pragma unroll
            for (int rr = 0; rr < 2; rr++) {
                int r = blockIdx.y*BLK + wm*32 + i*16 + g + rr*8;
                int c = blockIdx.x*BLK + wn*32 + j*8 + 2*t;
                #pragma unroll
                for (int cc = 0; cc < 2; cc++) {
                    float v = (acc[i][j][rr*2+cc] + bias[c+cc]) * scale;
                    if (HEAD_LAYOUT) {
                        int b_ = r / SS, s_ = r % SS;
                        int h_ = (c+cc) / DH, d_ = (c+cc) % DH;
                        out[((size_t)(b_*NH + h_)*SS + s_)*DH + d_] = v;
                    } else {
                        out[(size_t)r*DM + c+cc] = v;
                    }
                }
            }
        }
    }
}

// ------------------------------------------------------------
// Scores: per (b,h) SC = Qh @ Kh^T  (Q pre-scaled), mask==0 -> 1e-12
// ------------------------------------------------------------
__global__ __launch_bounds__(128)
void scores_mma(const int* __restrict__ masks) {
    const int bh = blockIdx.z;
    const int b_ = bh / NH;
    const float* Q  = g_qh + (size_t)bh*SS*DH + (size_t)blockIdx.y*BLK*DH;
    const float* Kp = g_kh + (size_t)bh*SS*DH + (size_t)blockIdx.x*BLK*DH;
    float* SC = g_sc + (size_t)bh*SS*SS;
    const int* M = masks + (size_t)b_*SS*SS;

    float acc[2][4][4] = {};
    gemm64<false>(Q, DH, Kp, DH, DH, acc);

    const int lane = threadIdx.x & 31, warp = threadIdx.x >> 5;
    const int g = lane >> 2, t = lane & 3;
    const int wm = warp >> 1, wn = warp & 1;
    #pragma unroll
    for (int i = 0; i < 2; i++) {
        #pragma unroll
        for (int j = 0; j < 4; j++) {
            #pragma unroll
            for (int rr = 0; rr < 2; rr++) {
                int r = blockIdx.y*BLK + wm*32 + i*16 + g + rr*8;
                int c = blockIdx.x*BLK + wn*32 + j*8 + 2*t;
                #pragma unroll
                for (int cc = 0; cc < 2; cc++) {
                    int m = M[(size_t)r*SS + c+cc];
                    SC[(size_t)r*SS + c+cc] = (m == 0) ? 1e-12f : acc[i][j][rr*2+cc];
                }
            }
        }
    }
}

// ------------------------------------------------------------
// Row softmax over g_sc, in place. One block per row.
// ------------------------------------------------------------
__global__ __launch_bounds__(256)
void softmax_kernel() {
    float* p = g_sc + (size_t)blockIdx.x * SS;
    const int t = threadIdx.x;
    __shared__ float red[256];

    float v[8];
    float lm = -INFINITY;
    #pragma unroll
    for (int i = 0; i < 8; i++) { v[i] = p[t + i*256]; lm = fmaxf(lm, v[i]); }
    red[t] = lm; __syncthreads();
    for (int s = 128; s > 0; s >>= 1) { if (t < s) red[t] = fmaxf(red[t], red[t+s]); __syncthreads(); }
    const float m = red[0]; __syncthreads();

    float ls = 0.f;
    #pragma unroll
    for (int i = 0; i < 8; i++) { v[i] = __expf(v[i] - m); ls += v[i]; }
    red[t] = ls; __syncthreads();
    for (int s = 128; s > 0; s >>= 1) { if (t < s) red[t] += red[t+s]; __syncthreads(); }
    const float inv = 1.0f / red[0];
    #pragma unroll
    for (int i = 0; i < 8; i++) p[t + i*256] = v[i] * inv;
}

// ------------------------------------------------------------
// P @ V: per (b,h), out[s,d] written into g_ao [B,S,H*Dh]
// ------------------------------------------------------------
__global__ __launch_bounds__(128)
void attnv_mma() {
    const int bh = blockIdx.z;
    const int b_ = bh / NH, h_ = bh % NH;
    const float* P = g_sc + (size_t)bh*SS*SS + (size_t)blockIdx.y*BLK*SS;
    const float* V = g_vh + (size_t)bh*SS*DH;   // [t][d], TRANSB path

    float acc[2][4][4] = {};
    gemm64<true>(P, SS, V, DH, SS, acc);

    const int lane = threadIdx.x & 31, warp = threadIdx.x >> 5;
    const int g = lane >> 2, t = lane & 3;
    const int wm = warp >> 1, wn = warp & 1;
    #pragma unroll
    for (int i = 0; i < 2; i++) {
        #pragma unroll
        for (int j = 0; j < 4; j++) {
            #pragma unroll
            for (int rr = 0; rr < 2; rr++) {
                int s_ = blockIdx.y*BLK + wm*32 + i*16 + g + rr*8;
                int d_ = wn*32 + j*8 + 2*t;
                #pragma unroll
                for (int cc = 0; cc < 2; cc++) {
                    g_ao[((size_t)(b_*SS + s_))*DM + h_*DH + d_ + cc] = acc[i][j][rr*2+cc];
                }
            }
        }
    }
}

// ============================================================
extern "C" void kernel_launch(void* const* d_in, const int* in_sizes, int n_in,
                              void* d_out, int out_size) {
    const float* q    = (const float*)d_in[0];
    const float* k    = (const float*)d_in[1];
    const float* v    = (const float*)d_in[2];
    const int*   msk  = (const int*)  d_in[3];
    const float* WQ_w = (const float*)d_in[4];
    const float* WQ_b = (const float*)d_in[5];
    const float* WK_w = (const float*)d_in[6];
    const float* WK_b = (const float*)d_in[7];
    const float* WV_w = (const float*)d_in[8];
    const float* WV_b = (const float*)d_in[9];
    const float* WO_w = (const float*)d_in[10];
    const float* WO_b = (const float*)d_in[11];
    float* out = (float*)d_out;

    float *qh, *kh, *vh, *ao;
    cudaGetSymbolAddress((void**)&qh, g_qh);
    cudaGetSymbolAddress((void**)&kh, g_kh);
    cudaGetSymbolAddress((void**)&vh, g_vh);
    cudaGetSymbolAddress((void**)&ao, g_ao);

    const float qscale = 1.0f / 8.0f;   // 1/sqrt(64)

    dim3 pg(DM/BLK, MROWS/BLK);         // (12, 64)
    proj_mma<true><<<pg, 128>>>(q, WQ_w, WQ_b, qh, qscale);
    proj_mma<true><<<pg, 128>>>(k, WK_w, WK_b, kh, 1.0f);
    proj_mma<true><<<pg, 128>>>(v, WV_w, WV_b, vh, 1.0f);

    dim3 sg(SS/BLK, SS/BLK, BB*NH);     // (32, 32, 24)
    scores_mma<<<sg, 128>>>(msk);

    softmax_kernel<<<BB*NH*SS, 256>>>();

    dim3 ag(1, SS/BLK, BB*NH);          // (1, 32, 24)
    attnv_mma<<<ag, 128>>>();

    proj_mma<false><<<pg, 128>>>(ao, WO_w, WO_b, out, 1.0f);
}

// round 4
// speedup vs baseline: 1.4161x; 1.3977x over previous
#include <cuda_runtime.h>
#include <cuda_bf16.h>
#include <cstdint>
#include <math.h>

#define BB 2
#define SS 2048
#define DM 768
#define NH 12
#define DH 64
#define MROWS (BB*SS)   // 4096

#define BLK 64          // proj block tile M and N
#define BK  32          // proj block tile K
#define SA  40          // proj smem row stride (bf16)

#define TQ 64           // flash q-tile rows
#define TK 64           // flash k-tile rows
#define LDQ 72          // flash smem row stride (bf16): 144B rows -> conflict-free frags

// ---- scratch (device globals; no allocation allowed) ----
__device__ float g_qh[(size_t)BB*NH*SS*DH];   // [B,H,S,Dh], Q pre-scaled by 1/8
__device__ float g_kh[(size_t)BB*NH*SS*DH];
__device__ float g_vh[(size_t)BB*NH*SS*DH];
__device__ float g_ao[(size_t)MROWS*DM];      // attention out, [B,S,H*Dh]

// ------------------------------------------------------------
// helpers
// ------------------------------------------------------------
__device__ __forceinline__ uint32_t bf2pack(__nv_bfloat16 a, __nv_bfloat16 b) {
    __nv_bfloat162 v; v.x = a; v.y = b;
    return *reinterpret_cast<uint32_t*>(&v);
}

__device__ __forceinline__ void split_pack(float x, float y, uint32_t& h, uint32_t& l) {
    __nv_bfloat16 hx = __float2bfloat16(x), hy = __float2bfloat16(y);
    h = bf2pack(hx, hy);
    l = bf2pack(__float2bfloat16(x - __bfloat162float(hx)),
                __float2bfloat16(y - __bfloat162float(hy)));
}

__device__ __forceinline__ void split_store(__nv_bfloat16* H, __nv_bfloat16* L,
                                            int idx, float x) {
    __nv_bfloat16 h = __float2bfloat16(x);
    float r = x - __bfloat162float(h);
    H[idx] = h;
    L[idx] = __float2bfloat16(r);
}

__device__ __forceinline__ void mma_bf16(float c[4],
                                         uint32_t a0, uint32_t a1, uint32_t a2, uint32_t a3,
                                         uint32_t b0, uint32_t b1) {
    asm volatile(
        "mma.sync.aligned.m16n8k16.row.col.f32.bf16.bf16.f32 "
        "{%0,%1,%2,%3},{%4,%5,%6,%7},{%8,%9},{%0,%1,%2,%3};"
        : "+f"(c[0]), "+f"(c[1]), "+f"(c[2]), "+f"(c[3])
        : "r"(a0), "r"(a1), "r"(a2), "r"(a3), "r"(b0), "r"(b1));
}

__device__ __forceinline__ void ldsm_x2_trans(uint32_t& r0, uint32_t& r1, uint32_t addr) {
    asm volatile("ldmatrix.sync.aligned.m8n8.x2.trans.shared.b16 {%0,%1}, [%2];"
                 : "=r"(r0), "=r"(r1) : "r"(addr));
}

// ============================================================
// FLASH ATTENTION: per block = 64 q-rows of one (b,h).
// Online softmax, S in registers, P->smem (reuses K bufs), V via ldmatrix.trans.
// grid (SS/TQ, BB*NH), 128 threads (4 warps, 2x2).
// ============================================================
__global__ __launch_bounds__(128)
void flash_attn(const int* __restrict__ masks) {
    extern __shared__ __nv_bfloat16 dsm[];
    __nv_bfloat16* Qh = dsm;
    __nv_bfloat16* Ql = dsm + 1*TQ*LDQ;
    __nv_bfloat16* Kh = dsm + 2*TQ*LDQ;   // reused as Ph
    __nv_bfloat16* Kl = dsm + 3*TQ*LDQ;   // reused as Pl
    __nv_bfloat16* Vh = dsm + 4*TQ*LDQ;
    __nv_bfloat16* Vl = dsm + 5*TQ*LDQ;
    __shared__ float wred[2][TQ], wsum[2][TQ], bcast[TQ], mrow[TQ], lrow[TQ], srow[TQ];

    const int bh = blockIdx.y;
    const int b_ = bh / NH, h_ = bh % NH;
    const int q0 = blockIdx.x * TQ;
    const float* Qg = g_qh + (size_t)bh*SS*DH + (size_t)q0*DH;
    const float* Kg = g_kh + (size_t)bh*SS*DH;
    const float* Vg = g_vh + (size_t)bh*SS*DH;
    const int*   M  = masks + (size_t)b_*SS*SS;

    const int tid = threadIdx.x, lane = tid & 31, warp = tid >> 5;
    const int g = lane >> 2, t = lane & 3;
    const int wm = warp >> 1, wn = warp & 1;
    const int sr = tid >> 1;            // staging row 0..63
    const int sc0 = (tid & 1) * 32;     // staging col base

    if (tid < TQ) { mrow[tid] = -INFINITY; lrow[tid] = 0.f; }

    // ---- stage Q once ----
    #pragma unroll
    for (int j = 0; j < 8; j++) {
        float4 v = *(const float4*)&Qg[sr*DH + sc0 + 4*j];
        int w = (sr*LDQ + sc0 + 4*j) >> 1;
        uint32_t h0,l0,h1,l1;
        split_pack(v.x, v.y, h0, l0);
        split_pack(v.z, v.w, h1, l1);
        ((uint32_t*)Qh)[w] = h0; ((uint32_t*)Qh)[w+1] = h1;
        ((uint32_t*)Ql)[w] = l0; ((uint32_t*)Ql)[w+1] = l1;
    }

    float O[2][4][4] = {};

    for (int kt = 0; kt < SS/TK; kt++) {
        __syncthreads();   // K/V/P buffers free to overwrite
        // ---- stage K, V tiles ----
        #pragma unroll
        for (int j = 0; j < 8; j++) {
            float4 kv = *(const float4*)&Kg[((size_t)kt*TK + sr)*DH + sc0 + 4*j];
            float4 vv = *(const float4*)&Vg[((size_t)kt*TK + sr)*DH + sc0 + 4*j];
            int w = (sr*LDQ + sc0 + 4*j) >> 1;
            uint32_t h0,l0,h1,l1;
            split_pack(kv.x, kv.y, h0, l0);
            split_pack(kv.z, kv.w, h1, l1);
            ((uint32_t*)Kh)[w] = h0; ((uint32_t*)Kh)[w+1] = h1;
            ((uint32_t*)Kl)[w] = l0; ((uint32_t*)Kl)[w+1] = l1;
            split_pack(vv.x, vv.y, h0, l0);
            split_pack(vv.z, vv.w, h1, l1);
            ((uint32_t*)Vh)[w] = h0; ((uint32_t*)Vh)[w+1] = h1;
            ((uint32_t*)Vl)[w] = l0; ((uint32_t*)Vl)[w+1] = l1;
        }
        __syncthreads();

        // ---- S = Q @ K^T (bf16x3) ----
        float S[2][4][4] = {};
        #pragma unroll
        for (int kc = 0; kc < DH; kc += 16) {
            uint32_t ah[2][4], al[2][4];
            #pragma unroll
            for (int i = 0; i < 2; i++) {
                int r0 = wm*32 + i*16 + g;
                ah[i][0] = *(const uint32_t*)&Qh[ r0   *LDQ + kc + 2*t    ];
                ah[i][1] = *(const uint32_t*)&Qh[(r0+8)*LDQ + kc + 2*t    ];
                ah[i][2] = *(const uint32_t*)&Qh[ r0   *LDQ + kc + 2*t + 8];
                ah[i][3] = *(const uint32_t*)&Qh[(r0+8)*LDQ + kc + 2*t + 8];
                al[i][0] = *(const uint32_t*)&Ql[ r0   *LDQ + kc + 2*t    ];
                al[i][1] = *(const uint32_t*)&Ql[(r0+8)*LDQ + kc + 2*t    ];
                al[i][2] = *(const uint32_t*)&Ql[ r0   *LDQ + kc + 2*t + 8];
                al[i][3] = *(const uint32_t*)&Ql[(r0+8)*LDQ + kc + 2*t + 8];
            }
            #pragma unroll
            for (int j = 0; j < 4; j++) {
                int n0 = wn*32 + j*8 + g;
                uint32_t bh0 = *(const uint32_t*)&Kh[n0*LDQ + kc + 2*t    ];
                uint32_t bh1 = *(const uint32_t*)&Kh[n0*LDQ + kc + 2*t + 8];
                uint32_t bl0 = *(const uint32_t*)&Kl[n0*LDQ + kc + 2*t    ];
                uint32_t bl1 = *(const uint32_t*)&Kl[n0*LDQ + kc + 2*t + 8];
                #pragma unroll
                for (int i = 0; i < 2; i++) {
                    mma_bf16(S[i][j], ah[i][0],ah[i][1],ah[i][2],ah[i][3], bh0, bh1);
                    mma_bf16(S[i][j], ah[i][0],ah[i][1],ah[i][2],ah[i][3], bl0, bl1);
                    mma_bf16(S[i][j], al[i][0],al[i][1],al[i][2],al[i][3], bh0, bh1);
                }
            }
        }

        // ---- mask quirk + warp-local row max ----
        float rmax[2][2] = {{-INFINITY,-INFINITY},{-INFINITY,-INFINITY}};
        #pragma unroll
        for (int i = 0; i < 2; i++) {
            #pragma unroll
            for (int rr = 0; rr < 2; rr++) {
                int rg = q0 + wm*32 + i*16 + g + rr*8;
                #pragma unroll
                for (int j = 0; j < 4; j++) {
                    int cb = kt*TK + wn*32 + j*8 + 2*t;
                    int2 mv = *(const int2*)&M[(size_t)rg*SS + cb];
                    float v0 = mv.x ? S[i][j][rr*2  ] : 1e-12f;
                    float v1 = mv.y ? S[i][j][rr*2+1] : 1e-12f;
                    S[i][j][rr*2] = v0; S[i][j][rr*2+1] = v1;
                    rmax[i][rr] = fmaxf(rmax[i][rr], fmaxf(v0, v1));
                }
                rmax[i][rr] = fmaxf(rmax[i][rr], __shfl_xor_sync(0xffffffffu, rmax[i][rr], 1));
                rmax[i][rr] = fmaxf(rmax[i][rr], __shfl_xor_sync(0xffffffffu, rmax[i][rr], 2));
                if (t == 0) wred[wn][wm*32 + i*16 + g + rr*8] = rmax[i][rr];
            }
        }
        __syncthreads();

        // ---- combine row stats ----
        if (tid < TQ) {
            float tm = fmaxf(wred[0][tid], wred[1][tid]);
            float mo = mrow[tid];
            float mn = fmaxf(mo, tm);
            mrow[tid] = mn;
            srow[tid] = __expf(mo - mn);
            bcast[tid] = mn;
        }
        __syncthreads();

        // ---- P = exp(S-m), write split P into K buffers, O rescale, row sums ----
        #pragma unroll
        for (int i = 0; i < 2; i++) {
            #pragma unroll
            for (int rr = 0; rr < 2; rr++) {
                int rl = wm*32 + i*16 + g + rr*8;
                float mn = bcast[rl], sc = srow[rl];
                float rs = 0.f;
                #pragma unroll
                for (int j = 0; j < 4; j++) {
                    O[i][j][rr*2  ] *= sc;
                    O[i][j][rr*2+1] *= sc;
                    float p0 = __expf(S[i][j][rr*2  ] - mn);
                    float p1 = __expf(S[i][j][rr*2+1] - mn);
                    rs += p0 + p1;
                    uint32_t ph, pl;
                    split_pack(p0, p1, ph, pl);
                    int w = (rl*LDQ + wn*32 + j*8 + 2*t) >> 1;
                    ((uint32_t*)Kh)[w] = ph;
                    ((uint32_t*)Kl)[w] = pl;
                }
                rs += __shfl_xor_sync(0xffffffffu, rs, 1);
                rs += __shfl_xor_sync(0xffffffffu, rs, 2);
                if (t == 0) wsum[wn][rl] = rs;
            }
        }
        __syncthreads();
        if (tid < TQ) lrow[tid] = lrow[tid]*srow[tid] + wsum[0][tid] + wsum[1][tid];

        // ---- O += P @ V (bf16x3), V fragments via ldmatrix.trans ----
        #pragma unroll
        for (int kc = 0; kc < TK; kc += 16) {
            uint32_t ah[2][4], al[2][4];
            #pragma unroll
            for (int i = 0; i < 2; i++) {
                int r0 = wm*32 + i*16 + g;
                ah[i][0] = *(const uint32_t*)&Kh[ r0   *LDQ + kc + 2*t    ];
                ah[i][1] = *(const uint32_t*)&Kh[(r0+8)*LDQ + kc + 2*t    ];
                ah[i][2] = *(const uint32_t*)&Kh[ r0   *LDQ + kc + 2*t + 8];
                ah[i][3] = *(const uint32_t*)&Kh[(r0+8)*LDQ + kc + 2*t + 8];
                al[i][0] = *(const uint32_t*)&Kl[ r0   *LDQ + kc + 2*t    ];
                al[i][1] = *(const uint32_t*)&Kl[(r0+8)*LDQ + kc + 2*t    ];
                al[i][2] = *(const uint32_t*)&Kl[ r0   *LDQ + kc + 2*t + 8];
                al[i][3] = *(const uint32_t*)&Kl[(r0+8)*LDQ + kc + 2*t + 8];
            }
            #pragma unroll
            for (int j = 0; j < 4; j++) {
                int n0 = wn*32 + j*8;
                int krow = kc + (lane & 15);
                uint32_t ad_h = (uint32_t)__cvta_generic_to_shared(&Vh[krow*LDQ + n0]);
                uint32_t ad_l = (uint32_t)__cvta_generic_to_shared(&Vl[krow*LDQ + n0]);
                uint32_t bh0, bh1, bl0, bl1;
                ldsm_x2_trans(bh0, bh1, ad_h);
                ldsm_x2_trans(bl0, bl1, ad_l);
                #pragma unroll
                for (int i = 0; i < 2; i++) {
                    mma_bf16(O[i][j], ah[i][0],ah[i][1],ah[i][2],ah[i][3], bh0, bh1);
                    mma_bf16(O[i][j], ah[i][0],ah[i][1],ah[i][2],ah[i][3], bl0, bl1);
                    mma_bf16(O[i][j], al[i][0],al[i][1],al[i][2],al[i][3], bh0, bh1);
                }
            }
        }
    }
    __syncthreads();

    // ---- epilogue: O /= l, write [B,S,H*Dh] ----
    #pragma unroll
    for (int i = 0; i < 2; i++) {
        #pragma unroll
        for (int rr = 0; rr < 2; rr++) {
            int rl = wm*32 + i*16 + g + rr*8;
            float inv = 1.0f / lrow[rl];
            int sg = q0 + rl;
            #pragma unroll
            for (int j = 0; j < 4; j++) {
                float2 o;
                o.x = O[i][j][rr*2  ] * inv;
                o.y = O[i][j][rr*2+1] * inv;
                *(float2*)&g_ao[((size_t)(b_*SS + sg))*DM + h_*DH + wn*32 + j*8 + 2*t] = o;
            }
        }
    }
}

// ============================================================
// Projection GEMM (unchanged from passing R3 kernel)
// ============================================================
__device__ __forceinline__ void gemm64(const float* __restrict__ A, int lda,
                                       const float* __restrict__ B, int ldb,
                                       int K, float acc[2][4][4]) {
    __shared__ __nv_bfloat16 Ah[BLK*SA], Al[BLK*SA];
    __shared__ __nv_bfloat16 Bh[BLK*SA], Bl[BLK*SA];

    const int tid  = threadIdx.x;
    const int lane = tid & 31, warp = tid >> 5;
    const int g = lane >> 2, t = lane & 3;
    const int wm = warp >> 1, wn = warp & 1;
    const int arow = tid >> 1;
    const int acb  = (tid & 1) * 16;

    for (int k0 = 0; k0 < K; k0 += BK) {
        #pragma unroll
        for (int j = 0; j < 4; j++) {
            float4 v = *(const float4*)&A[(size_t)arow * lda + k0 + acb + 4*j];
            int c = arow * SA + acb + 4*j;
            split_store(Ah, Al, c+0, v.x); split_store(Ah, Al, c+1, v.y);
            split_store(Ah, Al, c+2, v.z); split_store(Ah, Al, c+3, v.w);
        }
        #pragma unroll
        for (int j = 0; j < 4; j++) {
            float4 v = *(const float4*)&B[(size_t)arow * ldb + k0 + acb + 4*j];
            int c = arow * SA + acb + 4*j;
            split_store(Bh, Bl, c+0, v.x); split_store(Bh, Bl, c+1, v.y);
            split_store(Bh, Bl, c+2, v.z); split_store(Bh, Bl, c+3, v.w);
        }
        __syncthreads();
        #pragma unroll
        for (int kc = 0; kc < BK; kc += 16) {
            uint32_t ah[2][4], al[2][4];
            #pragma unroll
            for (int i = 0; i < 2; i++) {
                int r0 = wm*32 + i*16 + g;
                ah[i][0] = *(const uint32_t*)&Ah[ r0   *SA + kc + 2*t    ];
                ah[i][1] = *(const uint32_t*)&Ah[(r0+8)*SA + kc + 2*t    ];
                ah[i][2] = *(const uint32_t*)&Ah[ r0   *SA + kc + 2*t + 8];
                ah[i][3] = *(const uint32_t*)&Ah[(r0+8)*SA + kc + 2*t + 8];
                al[i][0] = *(const uint32_t*)&Al[ r0   *SA + kc + 2*t    ];
                al[i][1] = *(const uint32_t*)&Al[(r0+8)*SA + kc + 2*t    ];
                al[i][2] = *(const uint32_t*)&Al[ r0   *SA + kc + 2*t + 8];
                al[i][3] = *(const uint32_t*)&Al[(r0+8)*SA + kc + 2*t + 8];
            }
            #pragma unroll
            for (int j = 0; j < 4; j++) {
                int n0 = wn*32 + j*8 + g;
                uint32_t bh0 = *(const uint32_t*)&Bh[n0*SA + kc + 2*t    ];
                uint32_t bh1 = *(const uint32_t*)&Bh[n0*SA + kc + 2*t + 8];
                uint32_t bl0 = *(const uint32_t*)&Bl[n0*SA + kc + 2*t    ];
                uint32_t bl1 = *(const uint32_t*)&Bl[n0*SA + kc + 2*t + 8];
                #pragma unroll
                for (int i = 0; i < 2; i++) {
                    mma_bf16(acc[i][j], ah[i][0],ah[i][1],ah[i][2],ah[i][3], bh0, bh1);
                    mma_bf16(acc[i][j], ah[i][0],ah[i][1],ah[i][2],ah[i][3], bl0, bl1);
                    mma_bf16(acc[i][j], al[i][0],al[i][1],al[i][2],al[i][3], bh0, bh1);
                }
            }
        }
        __syncthreads();
    }
}

template<bool HEAD_LAYOUT>
__global__ __launch_bounds__(128)
void proj_mma(const float* __restrict__ X, const float* __restrict__ W,
              const float* __restrict__ bias, float* __restrict__ out, float scale) {
    float acc[2][4][4] = {};
    const float* Ap = X + (size_t)blockIdx.y * BLK * DM;
    const float* Bp = W + (size_t)blockIdx.x * BLK * DM;
    gemm64(Ap, DM, Bp, DM, DM, acc);

    const int lane = threadIdx.x & 31, warp = threadIdx.x >> 5;
    const int g = lane >> 2, t = lane & 3;
    const int wm = warp >> 1, wn = warp & 1;
    #pragma unroll
    for (int i = 0; i < 2; i++) {
        #pragma unroll
        for (int j = 0; j < 4; j++) {
            #pragma unroll
            for (int rr = 0; rr < 2; rr++) {
                int r = blockIdx.y*BLK + wm*32 + i*16 + g + rr*8;
                int c = blockIdx.x*BLK + wn*32 + j*8 + 2*t;
                #pragma unroll
                for (int cc = 0; cc < 2; cc++) {
                    float v = (acc[i][j][rr*2+cc] + bias[c+cc]) * scale;
                    if (HEAD_LAYOUT) {
                        int b_ = r / SS, s_ = r % SS;
                        int h_ = (c+cc) / DH, d_ = (c+cc) % DH;
                        out[((size_t)(b_*NH + h_)*SS + s_)*DH + d_] = v;
                    } else {
                        out[(size_t)r*DM + c+cc] = v;
                    }
                }
            }
        }
    }
}

// ============================================================
extern "C" void kernel_launch(void* const* d_in, const int* in_sizes, int n_in,
                              void* d_out, int out_size) {
    const float* q    = (const float*)d_in[0];
    const float* k    = (const float*)d_in[1];
    const float* v    = (const float*)d_in[2];
    const int*   msk  = (const int*)  d_in[3];
    const float* WQ_w = (const float*)d_in[4];
    const float* WQ_b = (const float*)d_in[5];
    const float* WK_w = (const float*)d_in[6];
    const float* WK_b = (const float*)d_in[7];
    const float* WV_w = (const float*)d_in[8];
    const float* WV_b = (const float*)d_in[9];
    const float* WO_w = (const float*)d_in[10];
    const float* WO_b = (const float*)d_in[11];
    float* out = (float*)d_out;

    float *qh, *kh, *vh, *ao;
    cudaGetSymbolAddress((void**)&qh, g_qh);
    cudaGetSymbolAddress((void**)&kh, g_kh);
    cudaGetSymbolAddress((void**)&vh, g_vh);
    cudaGetSymbolAddress((void**)&ao, g_ao);

    const int flash_smem = 6 * TQ * LDQ * (int)sizeof(__nv_bfloat16);  // 55296 B
    cudaFuncSetAttribute(flash_attn, cudaFuncAttributeMaxDynamicSharedMemorySize, flash_smem);

    const float qscale = 1.0f / 8.0f;   // 1/sqrt(64)

    dim3 pg(DM/BLK, MROWS/BLK);         // (12, 64)
    proj_mma<true><<<pg, 128>>>(q, WQ_w, WQ_b, qh, qscale);
    proj_mma<true><<<pg, 128>>>(k, WK_w, WK_b, kh, 1.0f);
    proj_mma<true><<<pg, 128>>>(v, WV_w, WV_b, vh, 1.0f);

    dim3 fg(SS/TQ, BB*NH);              // (32, 24)
    flash_attn<<<fg, 128, flash_smem>>>(msk);

    proj_mma<false><<<pg, 128>>>(ao, WO_w, WO_b, out, 1.0f);
}

// round 5
// speedup vs baseline: 2.2690x; 1.6024x over previous
#include <cuda_runtime.h>
#include <cuda_bf16.h>
#include <cstdint>
#include <math.h>

#define BB 2
#define SS 2048
#define DM 768
#define NH 12
#define DH 64
#define MROWS (BB*SS)   // 4096

#define BLK 64          // proj block tile M and N
#define BK  32          // proj block tile K
#define SA  40          // proj smem row stride (bf16)

#define TQ 64           // flash q-tile rows
#define TK 64           // flash k-tile rows
#define LDQ 72          // flash smem row stride (bf16)

// ---- scratch (device globals; no allocation allowed) ----
// split inputs (fp32 -> bf16 hi/lo)
__device__ __nv_bfloat16 g_xq_h[(size_t)MROWS*DM], g_xq_l[(size_t)MROWS*DM];
__device__ __nv_bfloat16 g_xk_h[(size_t)MROWS*DM], g_xk_l[(size_t)MROWS*DM];
__device__ __nv_bfloat16 g_xv_h[(size_t)MROWS*DM], g_xv_l[(size_t)MROWS*DM];
// split weights
__device__ __nv_bfloat16 g_wq_h[(size_t)DM*DM], g_wq_l[(size_t)DM*DM];
__device__ __nv_bfloat16 g_wk_h[(size_t)DM*DM], g_wk_l[(size_t)DM*DM];
__device__ __nv_bfloat16 g_wv_h[(size_t)DM*DM], g_wv_l[(size_t)DM*DM];
__device__ __nv_bfloat16 g_wo_h[(size_t)DM*DM], g_wo_l[(size_t)DM*DM];
// split projected heads [B,H,S,Dh]
__device__ __nv_bfloat16 g_qh_h[(size_t)BB*NH*SS*DH], g_qh_l[(size_t)BB*NH*SS*DH];
__device__ __nv_bfloat16 g_kh_h[(size_t)BB*NH*SS*DH], g_kh_l[(size_t)BB*NH*SS*DH];
__device__ __nv_bfloat16 g_vh_h[(size_t)BB*NH*SS*DH], g_vh_l[(size_t)BB*NH*SS*DH];
// split attention out [B,S,H*Dh]
__device__ __nv_bfloat16 g_ao_h[(size_t)MROWS*DM], g_ao_l[(size_t)MROWS*DM];

// ------------------------------------------------------------
// helpers
// ------------------------------------------------------------
__device__ __forceinline__ uint32_t bf2pack(__nv_bfloat16 a, __nv_bfloat16 b) {
    __nv_bfloat162 v; v.x = a; v.y = b;
    return *reinterpret_cast<uint32_t*>(&v);
}
__device__ __forceinline__ void split_pack(float x, float y, uint32_t& h, uint32_t& l) {
    __nv_bfloat16 hx = __float2bfloat16(x), hy = __float2bfloat16(y);
    h = bf2pack(hx, hy);
    l = bf2pack(__float2bfloat16(x - __bfloat162float(hx)),
                __float2bfloat16(y - __bfloat162float(hy)));
}
__device__ __forceinline__ void mma_bf16(float c[4],
                                         uint32_t a0, uint32_t a1, uint32_t a2, uint32_t a3,
                                         uint32_t b0, uint32_t b1) {
    asm volatile(
        "mma.sync.aligned.m16n8k16.row.col.f32.bf16.bf16.f32 "
        "{%0,%1,%2,%3},{%4,%5,%6,%7},{%8,%9},{%0,%1,%2,%3};"
        : "+f"(c[0]), "+f"(c[1]), "+f"(c[2]), "+f"(c[3])
        : "r"(a0), "r"(a1), "r"(a2), "r"(a3), "r"(b0), "r"(b1));
}
__device__ __forceinline__ uint32_t sptr(const void* p) {
    return (uint32_t)__cvta_generic_to_shared(p);
}
__device__ __forceinline__ void ldsm_x4(uint32_t& r0, uint32_t& r1, uint32_t& r2, uint32_t& r3, uint32_t a) {
    asm volatile("ldmatrix.sync.aligned.m8n8.x4.shared.b16 {%0,%1,%2,%3}, [%4];"
                 : "=r"(r0), "=r"(r1), "=r"(r2), "=r"(r3) : "r"(a));
}
__device__ __forceinline__ void ldsm_x2(uint32_t& r0, uint32_t& r1, uint32_t a) {
    asm volatile("ldmatrix.sync.aligned.m8n8.x2.shared.b16 {%0,%1}, [%2];"
                 : "=r"(r0), "=r"(r1) : "r"(a));
}
__device__ __forceinline__ void ldsm_x2_trans(uint32_t& r0, uint32_t& r1, uint32_t a) {
    asm volatile("ldmatrix.sync.aligned.m8n8.x2.trans.shared.b16 {%0,%1}, [%2];"
                 : "=r"(r0), "=r"(r1) : "r"(a));
}
__device__ __forceinline__ void cp16(uint32_t s, const void* g) {
    asm volatile("cp.async.cg.shared.global [%0], [%1], 16;" :: "r"(s), "l"(g));
}
__device__ __forceinline__ void cp_commit() { asm volatile("cp.async.commit_group;"); }
__device__ __forceinline__ void cp_wait0()  { asm volatile("cp.async.wait_group 0;"); }

// ============================================================
// split fp32 -> bf16 hi/lo, 4 elems per thread
// ============================================================
__global__ __launch_bounds__(256)
void split4(const float* __restrict__ x, __nv_bfloat16* __restrict__ h,
            __nv_bfloat16* __restrict__ l, int n) {
    int i = (blockIdx.x * blockDim.x + threadIdx.x) * 4;
    if (i >= n) return;
    float4 v = *(const float4*)&x[i];
    uint32_t h0, l0, h1, l1;
    split_pack(v.x, v.y, h0, l0);
    split_pack(v.z, v.w, h1, l1);
    uint32_t* H = (uint32_t*)h; uint32_t* L = (uint32_t*)l;
    H[(i>>1)  ] = h0; H[(i>>1)+1] = h1;
    L[(i>>1)  ] = l0; L[(i>>1)+1] = l1;
}

// ============================================================
// Projection GEMM on pre-split bf16: C = A @ B^T (+bias)*scale
// A: [4096][768] split pair, B: [768][768] split pair (torch W layout).
// MODE 0: write split bf16 to head layout [B,H,S,Dh].
// MODE 1: write fp32 to Of [4096][768].
// 128 threads, 64x64 tile, cp.async staging, ldmatrix frags, bf16x3.
// ============================================================
template<int MODE>
__global__ __launch_bounds__(128)
void proj_bf16(const __nv_bfloat16* __restrict__ Agh, const __nv_bfloat16* __restrict__ Agl,
               const __nv_bfloat16* __restrict__ Bgh, const __nv_bfloat16* __restrict__ Bgl,
               const float* __restrict__ bias, float scale,
               __nv_bfloat16* __restrict__ Oh, __nv_bfloat16* __restrict__ Ol,
               float* __restrict__ Of) {
    __shared__ __nv_bfloat16 Ah[BLK*SA], Al[BLK*SA], Bh[BLK*SA], Bl[BLK*SA];

    const int tid = threadIdx.x, lane = tid & 31, warp = tid >> 5;
    const int g = lane >> 2, t = lane & 3, l15 = lane & 15;
    const int wm = warp >> 1, wn = warp & 1;
    const size_t arow0 = (size_t)blockIdx.y * BLK;
    const size_t brow0 = (size_t)blockIdx.x * BLK;
    const int srow = tid >> 1, scb = (tid & 1) * 16;

    float acc[2][4][4] = {};

    for (int k0 = 0; k0 < DM; k0 += BK) {
        __syncthreads();
        #pragma unroll
        for (int j = 0; j < 2; j++) {
            int c = scb + 8*j;
            cp16(sptr(&Ah[srow*SA + c]), &Agh[(arow0+srow)*DM + k0 + c]);
            cp16(sptr(&Al[srow*SA + c]), &Agl[(arow0+srow)*DM + k0 + c]);
            cp16(sptr(&Bh[srow*SA + c]), &Bgh[(brow0+srow)*DM + k0 + c]);
            cp16(sptr(&Bl[srow*SA + c]), &Bgl[(brow0+srow)*DM + k0 + c]);
        }
        cp_commit(); cp_wait0();
        __syncthreads();

        #pragma unroll
        for (int kc = 0; kc < BK; kc += 16) {
            uint32_t ah[2][4], al[2][4];
            #pragma unroll
            for (int i = 0; i < 2; i++) {
                int ar = wm*32 + i*16 + l15;
                int ac = kc + ((lane >> 4) << 3);
                ldsm_x4(ah[i][0], ah[i][1], ah[i][2], ah[i][3], sptr(&Ah[ar*SA + ac]));
                ldsm_x4(al[i][0], al[i][1], al[i][2], al[i][3], sptr(&Al[ar*SA + ac]));
            }
            #pragma unroll
            for (int j = 0; j < 4; j++) {
                int br = wn*32 + j*8 + (l15 & 7);
                int bc = kc + ((l15 >> 3) << 3);
                uint32_t bh0, bh1, bl0, bl1;
                ldsm_x2(bh0, bh1, sptr(&Bh[br*SA + bc]));
                ldsm_x2(bl0, bl1, sptr(&Bl[br*SA + bc]));
                #pragma unroll
                for (int i = 0; i < 2; i++) {
                    mma_bf16(acc[i][j], ah[i][0],ah[i][1],ah[i][2],ah[i][3], bh0, bh1);
                    mma_bf16(acc[i][j], ah[i][0],ah[i][1],ah[i][2],ah[i][3], bl0, bl1);
                    mma_bf16(acc[i][j], al[i][0],al[i][1],al[i][2],al[i][3], bh0, bh1);
                }
            }
        }
    }

    #pragma unroll
    for (int i = 0; i < 2; i++) {
        #pragma unroll
        for (int rr = 0; rr < 2; rr++) {
            int r = (int)arow0 + wm*32 + i*16 + g + rr*8;
            #pragma unroll
            for (int j = 0; j < 4; j++) {
                int c = (int)brow0 + wn*32 + j*8 + 2*t;
                float v0 = (acc[i][j][rr*2  ] + bias[c  ]) * scale;
                float v1 = (acc[i][j][rr*2+1] + bias[c+1]) * scale;
                if (MODE == 0) {
                    int b_ = r / SS, s_ = r % SS;
                    int h_ = c / DH, d_ = c % DH;
                    size_t idx = ((size_t)(b_*NH + h_)*SS + s_)*DH + d_;
                    uint32_t ph, pl;
                    split_pack(v0, v1, ph, pl);
                    *(uint32_t*)&Oh[idx] = ph;
                    *(uint32_t*)&Ol[idx] = pl;
                } else {
                    float2 o; o.x = v0; o.y = v1;
                    *(float2*)&Of[(size_t)r*DM + c] = o;
                }
            }
        }
    }
}

// ============================================================
// FLASH ATTENTION on pre-split bf16 heads; writes split bf16 ao.
// grid (SS/TQ, BB*NH), 128 threads (4 warps, 2x2).
// ============================================================
__global__ __launch_bounds__(128)
void flash_attn(const int* __restrict__ masks) {
    extern __shared__ __nv_bfloat16 dsm[];
    __nv_bfloat16* Qh = dsm;
    __nv_bfloat16* Ql = dsm + 1*TQ*LDQ;
    __nv_bfloat16* Kh = dsm + 2*TQ*LDQ;   // reused as Ph
    __nv_bfloat16* Kl = dsm + 3*TQ*LDQ;   // reused as Pl
    __nv_bfloat16* Vh = dsm + 4*TQ*LDQ;
    __nv_bfloat16* Vl = dsm + 5*TQ*LDQ;
    __shared__ float wred[2][TQ], wsum[2][TQ], bcast[TQ], mrow[TQ], lrow[TQ], srow[TQ];

    const int bh = blockIdx.y;
    const int b_ = bh / NH, h_ = bh % NH;
    const int q0 = blockIdx.x * TQ;
    const size_t qoff = ((size_t)bh*SS + q0)*DH;
    const size_t koff0 = (size_t)bh*SS*DH;
    const int* M = masks + (size_t)b_*SS*SS;

    const int tid = threadIdx.x, lane = tid & 31, warp = tid >> 5;
    const int g = lane >> 2, t = lane & 3, l15 = lane & 15;
    const int wm = warp >> 1, wn = warp & 1;
    const int sr = tid >> 1;            // staging row 0..63
    const int sc0 = (tid & 1) * 32;     // staging col base

    if (tid < TQ) { mrow[tid] = -INFINITY; lrow[tid] = 0.f; }

    // ---- stage Q once (cp.async) ----
    #pragma unroll
    for (int j = 0; j < 4; j++) {
        int c = sc0 + 8*j;
        cp16(sptr(&Qh[sr*LDQ + c]), &g_qh_h[qoff + (size_t)sr*DH + c]);
        cp16(sptr(&Ql[sr*LDQ + c]), &g_qh_l[qoff + (size_t)sr*DH + c]);
    }
    cp_commit();

    float O[2][4][4] = {};

    for (int kt = 0; kt < SS/TK; kt++) {
        __syncthreads();   // K/V/P buffers free to overwrite
        const size_t koff = koff0 + (size_t)kt*TK*DH;
        #pragma unroll
        for (int j = 0; j < 4; j++) {
            int c = sc0 + 8*j;
            cp16(sptr(&Kh[sr*LDQ + c]), &g_kh_h[koff + (size_t)sr*DH + c]);
            cp16(sptr(&Kl[sr*LDQ + c]), &g_kh_l[koff + (size_t)sr*DH + c]);
            cp16(sptr(&Vh[sr*LDQ + c]), &g_vh_h[koff + (size_t)sr*DH + c]);
            cp16(sptr(&Vl[sr*LDQ + c]), &g_vh_l[koff + (size_t)sr*DH + c]);
        }
        cp_commit(); cp_wait0();
        __syncthreads();

        // ---- S = Q @ K^T (bf16x3) ----
        float S[2][4][4] = {};
        #pragma unroll
        for (int kc = 0; kc < DH; kc += 16) {
            uint32_t ah[2][4], al[2][4];
            #pragma unroll
            for (int i = 0; i < 2; i++) {
                int ar = wm*32 + i*16 + l15;
                int ac = kc + ((lane >> 4) << 3);
                ldsm_x4(ah[i][0], ah[i][1], ah[i][2], ah[i][3], sptr(&Qh[ar*LDQ + ac]));
                ldsm_x4(al[i][0], al[i][1], al[i][2], al[i][3], sptr(&Ql[ar*LDQ + ac]));
            }
            #pragma unroll
            for (int j = 0; j < 4; j++) {
                int br = wn*32 + j*8 + (l15 & 7);
                int bc = kc + ((l15 >> 3) << 3);
                uint32_t bh0, bh1, bl0, bl1;
                ldsm_x2(bh0, bh1, sptr(&Kh[br*LDQ + bc]));
                ldsm_x2(bl0, bl1, sptr(&Kl[br*LDQ + bc]));
                #pragma unroll
                for (int i = 0; i < 2; i++) {
                    mma_bf16(S[i][j], ah[i][0],ah[i][1],ah[i][2],ah[i][3], bh0, bh1);
                    mma_bf16(S[i][j], ah[i][0],ah[i][1],ah[i][2],ah[i][3], bl0, bl1);
                    mma_bf16(S[i][j], al[i][0],al[i][1],al[i][2],al[i][3], bh0, bh1);
                }
            }
        }

        // ---- mask quirk + warp-local row max ----
        float rmax[2][2] = {{-INFINITY,-INFINITY},{-INFINITY,-INFINITY}};
        #pragma unroll
        for (int i = 0; i < 2; i++) {
            #pragma unroll
            for (int rr = 0; rr < 2; rr++) {
                int rg = q0 + wm*32 + i*16 + g + rr*8;
                #pragma unroll
                for (int j = 0; j < 4; j++) {
                    int cb = kt*TK + wn*32 + j*8 + 2*t;
                    int2 mv = *(const int2*)&M[(size_t)rg*SS + cb];
                    float v0 = mv.x ? S[i][j][rr*2  ] : 1e-12f;
                    float v1 = mv.y ? S[i][j][rr*2+1] : 1e-12f;
                    S[i][j][rr*2] = v0; S[i][j][rr*2+1] = v1;
                    rmax[i][rr] = fmaxf(rmax[i][rr], fmaxf(v0, v1));
                }
                rmax[i][rr] = fmaxf(rmax[i][rr], __shfl_xor_sync(0xffffffffu, rmax[i][rr], 1));
                rmax[i][rr] = fmaxf(rmax[i][rr], __shfl_xor_sync(0xffffffffu, rmax[i][rr], 2));
                if (t == 0) wred[wn][wm*32 + i*16 + g + rr*8] = rmax[i][rr];
            }
        }
        __syncthreads();

        if (tid < TQ) {
            float tm = fmaxf(wred[0][tid], wred[1][tid]);
            float mo = mrow[tid];
            float mn = fmaxf(mo, tm);
            mrow[tid] = mn;
            srow[tid] = __expf(mo - mn);
            bcast[tid] = mn;
        }
        __syncthreads();

        // ---- P = exp(S-m) -> split into K buffers; O rescale; row sums ----
        #pragma unroll
        for (int i = 0; i < 2; i++) {
            #pragma unroll
            for (int rr = 0; rr < 2; rr++) {
                int rl = wm*32 + i*16 + g + rr*8;
                float mn = bcast[rl], sc = srow[rl];
                float rs = 0.f;
                #pragma unroll
                for (int j = 0; j < 4; j++) {
                    O[i][j][rr*2  ] *= sc;
                    O[i][j][rr*2+1] *= sc;
                    float p0 = __expf(S[i][j][rr*2  ] - mn);
                    float p1 = __expf(S[i][j][rr*2+1] - mn);
                    rs += p0 + p1;
                    uint32_t ph, pl;
                    split_pack(p0, p1, ph, pl);
                    int w = (rl*LDQ + wn*32 + j*8 + 2*t) >> 1;
                    ((uint32_t*)Kh)[w] = ph;
                    ((uint32_t*)Kl)[w] = pl;
                }
                rs += __shfl_xor_sync(0xffffffffu, rs, 1);
                rs += __shfl_xor_sync(0xffffffffu, rs, 2);
                if (t == 0) wsum[wn][rl] = rs;
            }
        }
        __syncthreads();
        if (tid < TQ) lrow[tid] = lrow[tid]*srow[tid] + wsum[0][tid] + wsum[1][tid];

        // ---- O += P @ V (bf16x3) ----
        #pragma unroll
        for (int kc = 0; kc < TK; kc += 16) {
            uint32_t ah[2][4], al[2][4];
            #pragma unroll
            for (int i = 0; i < 2; i++) {
                int ar = wm*32 + i*16 + l15;
                int ac = kc + ((lane >> 4) << 3);
                ldsm_x4(ah[i][0], ah[i][1], ah[i][2], ah[i][3], sptr(&Kh[ar*LDQ + ac]));
                ldsm_x4(al[i][0], al[i][1], al[i][2], al[i][3], sptr(&Kl[ar*LDQ + ac]));
            }
            #pragma unroll
            for (int j = 0; j < 4; j++) {
                int n0 = wn*32 + j*8;
                int krow = kc + l15;
                uint32_t bh0, bh1, bl0, bl1;
                ldsm_x2_trans(bh0, bh1, sptr(&Vh[krow*LDQ + n0]));
                ldsm_x2_trans(bl0, bl1, sptr(&Vl[krow*LDQ + n0]));
                #pragma unroll
                for (int i = 0; i < 2; i++) {
                    mma_bf16(O[i][j], ah[i][0],ah[i][1],ah[i][2],ah[i][3], bh0, bh1);
                    mma_bf16(O[i][j], ah[i][0],ah[i][1],ah[i][2],ah[i][3], bl0, bl1);
                    mma_bf16(O[i][j], al[i][0],al[i][1],al[i][2],al[i][3], bh0, bh1);
                }
            }
        }
    }
    __syncthreads();

    // ---- epilogue: O /= l, split-write to g_ao_h/l [B,S,H*Dh] ----
    #pragma unroll
    for (int i = 0; i < 2; i++) {
        #pragma unroll
        for (int rr = 0; rr < 2; rr++) {
            int rl = wm*32 + i*16 + g + rr*8;
            float inv = 1.0f / lrow[rl];
            int sg = q0 + rl;
            #pragma unroll
            for (int j = 0; j < 4; j++) {
                float o0 = O[i][j][rr*2  ] * inv;
                float o1 = O[i][j][rr*2+1] * inv;
                size_t idx = ((size_t)(b_*SS + sg))*DM + h_*DH + wn*32 + j*8 + 2*t;
                uint32_t ph, pl;
                split_pack(o0, o1, ph, pl);
                *(uint32_t*)&g_ao_h[idx] = ph;
                *(uint32_t*)&g_ao_l[idx] = pl;
            }
        }
    }
}

// ============================================================
extern "C" void kernel_launch(void* const* d_in, const int* in_sizes, int n_in,
                              void* d_out, int out_size) {
    const float* q    = (const float*)d_in[0];
    const float* k    = (const float*)d_in[1];
    const float* v    = (const float*)d_in[2];
    const int*   msk  = (const int*)  d_in[3];
    const float* WQ_w = (const float*)d_in[4];
    const float* WQ_b = (const float*)d_in[5];
    const float* WK_w = (const float*)d_in[6];
    const float* WK_b = (const float*)d_in[7];
    const float* WV_w = (const float*)d_in[8];
    const float* WV_b = (const float*)d_in[9];
    const float* WO_w = (const float*)d_in[10];
    const float* WO_b = (const float*)d_in[11];
    float* out = (float*)d_out;

    // resolve device-global addresses
    __nv_bfloat16 *xq_h,*xq_l,*xk_h,*xk_l,*xv_h,*xv_l;
    __nv_bfloat16 *wq_h,*wq_l,*wk_h,*wk_l,*wv_h,*wv_l,*wo_h,*wo_l;
    __nv_bfloat16 *qh_h,*qh_l,*kh_h,*kh_l,*vh_h,*vh_l,*ao_h,*ao_l;
    cudaGetSymbolAddress((void**)&xq_h, g_xq_h); cudaGetSymbolAddress((void**)&xq_l, g_xq_l);
    cudaGetSymbolAddress((void**)&xk_h, g_xk_h); cudaGetSymbolAddress((void**)&xk_l, g_xk_l);
    cudaGetSymbolAddress((void**)&xv_h, g_xv_h); cudaGetSymbolAddress((void**)&xv_l, g_xv_l);
    cudaGetSymbolAddress((void**)&wq_h, g_wq_h); cudaGetSymbolAddress((void**)&wq_l, g_wq_l);
    cudaGetSymbolAddress((void**)&wk_h, g_wk_h); cudaGetSymbolAddress((void**)&wk_l, g_wk_l);
    cudaGetSymbolAddress((void**)&wv_h, g_wv_h); cudaGetSymbolAddress((void**)&wv_l, g_wv_l);
    cudaGetSymbolAddress((void**)&wo_h, g_wo_h); cudaGetSymbolAddress((void**)&wo_l, g_wo_l);
    cudaGetSymbolAddress((void**)&qh_h, g_qh_h); cudaGetSymbolAddress((void**)&qh_l, g_qh_l);
    cudaGetSymbolAddress((void**)&kh_h, g_kh_h); cudaGetSymbolAddress((void**)&kh_l, g_kh_l);
    cudaGetSymbolAddress((void**)&vh_h, g_vh_h); cudaGetSymbolAddress((void**)&vh_l, g_vh_l);
    cudaGetSymbolAddress((void**)&ao_h, g_ao_h); cudaGetSymbolAddress((void**)&ao_l, g_ao_l);

    const int flash_smem = 6 * TQ * LDQ * (int)sizeof(__nv_bfloat16);  // 55296 B
    cudaFuncSetAttribute(flash_attn, cudaFuncAttributeMaxDynamicSharedMemorySize, flash_smem);

    const float qscale = 1.0f / 8.0f;   // 1/sqrt(64)

    // ---- split inputs & weights to bf16 hi/lo ----
    const int nx = MROWS*DM, nw = DM*DM;
    split4<<<(nx/4 + 255)/256, 256>>>(q, xq_h, xq_l, nx);
    split4<<<(nx/4 + 255)/256, 256>>>(k, xk_h, xk_l, nx);
    split4<<<(nx/4 + 255)/256, 256>>>(v, xv_h, xv_l, nx);
    split4<<<(nw/4 + 255)/256, 256>>>(WQ_w, wq_h, wq_l, nw);
    split4<<<(nw/4 + 255)/256, 256>>>(WK_w, wk_h, wk_l, nw);
    split4<<<(nw/4 + 255)/256, 256>>>(WV_w, wv_h, wv_l, nw);
    split4<<<(nw/4 + 255)/256, 256>>>(WO_w, wo_h, wo_l, nw);

    // ---- QKV projections (write split heads) ----
    dim3 pg(DM/BLK, MROWS/BLK);         // (12, 64)
    proj_bf16<0><<<pg, 128>>>(xq_h, xq_l, wq_h, wq_l, WQ_b, qscale, qh_h, qh_l, nullptr);
    proj_bf16<0><<<pg, 128>>>(xk_h, xk_l, wk_h, wk_l, WK_b, 1.0f,   kh_h, kh_l, nullptr);
    proj_bf16<0><<<pg, 128>>>(xv_h, xv_l, wv_h, wv_l, WV_b, 1.0f,   vh_h, vh_l, nullptr);

    // ---- fused attention ----
    dim3 fg(SS/TQ, BB*NH);              // (32, 24)
    flash_attn<<<fg, 128, flash_smem>>>(msk);

    // ---- output projection (fp32 out) ----
    proj_bf16<1><<<pg, 128>>>(ao_h, ao_l, wo_h, wo_l, WO_b, 1.0f, nullptr, nullptr, out);
}